// round 14
// baseline (speedup 1.0000x reference)
#include <cuda_runtime.h>
#include <math_constants.h>

#define BB 512
#define SS 200
#define UU 50
#define DD 32
#define NITER 13          // ceil(50 rows / 4 rows-per-iter)
#define NEG_INF_V (-1e9f)

__global__ __launch_bounds__(256)
void DIB_attn_kernel(const float* __restrict__ cur_user,   // [B, D]
                     const float* __restrict__ sim_user,   // [B, S, U, D]
                     const float* __restrict__ cur_item,   // [B, S, D]
                     const int* __restrict__ mask,          // [B, S, U] (bool -> int32)
                     float* __restrict__ out)               // [B, S, D]
{
    const unsigned FULL = 0xffffffffu;
    int w    = threadIdx.x >> 5;
    int lane = threadIdx.x & 31;
    int sub  = lane >> 3;       // 0..3 : row within 4-row group
    int quad = lane & 7;        // 0..7 : dims quad*4 .. quad*4+3

    int b = blockIdx.y;                          // no division
    int gwarp = b * SS + blockIdx.x * 8 + w;     // 25 blocks/b * 8 warps = 200 = SS

    // ---- Mask: 2 coalesced loads + 2 ballots -> 50-bit "unmasked" bitmap ----
    const int* mrow = mask + (long long)gwarp * UU;
    int m0 = __ldg(mrow + lane);                        // u = 0..31
    unsigned bits0 = __ballot_sync(FULL, m0 == 0);
    int u2 = 32 + lane;
    int m1 = (u2 < UU) ? __ldg(mrow + u2) : 1;          // u = 32..49
    unsigned bits1 = __ballot_sync(FULL, (u2 < UU) && (m1 == 0));
    bool degen = (bits0 | bits1) == 0u;                 // all masked
    if (degen) { bits0 = 0xffffffffu; bits1 = 0x3ffffu; }  // load all 50 rows

    float4 cu = __ldg((const float4*)(cur_user + b * DD) + quad);
    const float* tile = sim_user + (long long)gwarp * (UU * DD);

    // ---- Predicated tile load (R7 structure: separate loop, v[]+un[] live
    //      across the score loop -> ptxas front-batches the 13 LDG.128).
    //      Masked rows: 128B line never fetched.
    float4 v[NITER];
    bool   un[NITER];
    #pragma unroll
    for (int i = 0; i < NITER; i++) {
        int u = i * 4 + sub;
        un[i] = (u < UU) &&
            (((u < 32 ? (bits0 >> u) : (bits1 >> (u - 32))) & 1u) != 0u);
        float4 vv = make_float4(0.f, 0.f, 0.f, 0.f);
        if (un[i]) vv = __ldg((const float4*)(tile + u * DD) + quad);
        v[i] = vv;
    }

    // ---- Dot products + scores (masked/degen-load -> handled via un[]) ----
    float sc[NITER];
    #pragma unroll
    for (int i = 0; i < NITER; i++) {
        float p = v[i].x * cu.x + v[i].y * cu.y + v[i].z * cu.z + v[i].w * cu.w;
        p += __shfl_xor_sync(FULL, p, 1);
        p += __shfl_xor_sync(FULL, p, 2);
        p += __shfl_xor_sync(FULL, p, 4);               // 8-lane group holds score
        sc[i] = un[i] ? p : -CUDART_INF_F;              // not-loaded -> weight 0
    }

    // ---- No-max softmax (scores are dots of N(0,1) 32-dim vectors, |p|<~35
    //      << 88 so expf is safe; ratio self-normalizes; validated R11-R13).
    //      degen: all rows loaded, e forced to 1 -> uniform 1/50 = reference.
    float e[NITER];
    float s = 0.f;
    #pragma unroll
    for (int i = 0; i < NITER; i++) {
        e[i] = degen ? (un[i] ? 1.0f : 0.0f) : __expf(sc[i]);   // expf(-inf)=0
        s += e[i];
    }
    s += __shfl_xor_sync(FULL, s, 8);
    s += __shfl_xor_sync(FULL, s, 16);
    float inv = __frcp_rn(s);                   // s>0 always (degen -> s=50)

    // ---- Weighted sum (weights lane-local; v=0 for skipped rows) ----
    float4 o = make_float4(0.f, 0.f, 0.f, 0.f);
    #pragma unroll
    for (int i = 0; i < NITER; i++) {
        float a = e[i] * inv;
        o.x = fmaf(a, v[i].x, o.x);
        o.y = fmaf(a, v[i].y, o.y);
        o.z = fmaf(a, v[i].z, o.z);
        o.w = fmaf(a, v[i].w, o.w);
    }

    // Reduce partial outputs across the 4 sub groups (same dims, different rows).
    #pragma unroll
    for (int off = 8; off <= 16; off <<= 1) {
        o.x += __shfl_xor_sync(FULL, o.x, off);
        o.y += __shfl_xor_sync(FULL, o.y, off);
        o.z += __shfl_xor_sync(FULL, o.z, off);
        o.w += __shfl_xor_sync(FULL, o.w, off);
    }

    // sub==0 lanes (8 of them) write the 128B output row.
    if (sub == 0) {
        float4 ci = __ldg((const float4*)(cur_item + (long long)gwarp * DD) + quad);
        float4 r = make_float4(o.x + ci.x, o.y + ci.y, o.z + ci.z, o.w + ci.w);
        ((float4*)(out + (long long)gwarp * DD))[quad] = r;
    }
}

extern "C" void kernel_launch(void* const* d_in, const int* in_sizes, int n_in,
                              void* d_out, int out_size) {
    // Select inputs by element count (robust to ordering):
    const float* cur_user = nullptr;
    const float* sim_user = nullptr;
    const float* cur_item = nullptr;
    const int*   mask     = nullptr;
    for (int i = 0; i < n_in; i++) {
        switch (in_sizes[i]) {
            case 16384:     cur_user = (const float*)d_in[i]; break;
            case 163840000: sim_user = (const float*)d_in[i]; break;
            case 3276800:   cur_item = (const float*)d_in[i]; break;
            case 5120000:   mask     = (const int*)d_in[i];   break;
        }
    }
    float* out = (float*)d_out;

    dim3 grid(SS / 8, BB);                  // 25 x 512 blocks, 8 warps/block
    DIB_attn_kernel<<<grid, 256>>>(cur_user, sim_user, cur_item, mask, out);
}

// round 15
// speedup vs baseline: 1.2899x; 1.2899x over previous
#include <cuda_runtime.h>
#include <math_constants.h>

#define BB 512
#define SS 200
#define UU 50
#define DD 32
#define NITER 13          // ceil(50 rows / 4 rows-per-iter)
#define NEG_INF_V (-1e9f)

__global__ __launch_bounds__(256, 4)   // cap 64 regs -> 32 warps/SM, keep batch
void DIB_attn_kernel(const float* __restrict__ cur_user,   // [B, D]
                     const float* __restrict__ sim_user,   // [B, S, U, D]
                     const float* __restrict__ cur_item,   // [B, S, D]
                     const int* __restrict__ mask,          // [B, S, U] (bool -> int32)
                     float* __restrict__ out)               // [B, S, D]
{
    const unsigned FULL = 0xffffffffu;
    int w    = threadIdx.x >> 5;
    int lane = threadIdx.x & 31;
    int sub  = lane >> 3;       // 0..3 : row within 4-row group
    int quad = lane & 7;        // 0..7 : dims quad*4 .. quad*4+3

    int b = blockIdx.y;                          // no division
    int gwarp = b * SS + blockIdx.x * 8 + w;     // 25 blocks/b * 8 warps = 200 = SS

    // ---- Mask: 2 coalesced loads + 2 ballots -> 50-bit "unmasked" bitmap ----
    const int* mrow = mask + (long long)gwarp * UU;
    int m0 = __ldg(mrow + lane);                        // u = 0..31
    unsigned bits0 = __ballot_sync(FULL, m0 == 0);
    int u2 = 32 + lane;
    int m1 = (u2 < UU) ? __ldg(mrow + u2) : 1;          // u = 32..49
    unsigned bits1 = __ballot_sync(FULL, (u2 < UU) && (m1 == 0));
    if ((bits0 | bits1) == 0u) {                        // degen: all masked ->
        bits0 = 0xffffffffu; bits1 = 0x3ffffu;          // uniform over all 50,
    }                                                   // matches reference exactly

    float4 cu = __ldg((const float4*)(cur_user + b * DD) + quad);
    const float* tile = sim_user + (long long)gwarp * (UU * DD);

    // ---- Pass 1: predicated front-batched loads, dot products ----
    // (masked rows: their 128B line is owned by 8 predicated-off lanes -> no
    //  memory request)
    float4 v[NITER];
    float  sc[NITER];
    #pragma unroll
    for (int i = 0; i < NITER; i++) {
        int u = i * 4 + sub;
        bool un = (u < UU) &&
            (((u < 32 ? (bits0 >> u) : (bits1 >> (u - 32))) & 1u) != 0u);
        float4 vv = make_float4(0.f, 0.f, 0.f, 0.f);
        if (un) vv = __ldg((const float4*)(tile + u * DD) + quad);
        v[i] = vv;

        float p = vv.x * cu.x + vv.y * cu.y + vv.z * cu.z + vv.w * cu.w;
        p += __shfl_xor_sync(FULL, p, 1);
        p += __shfl_xor_sync(FULL, p, 2);
        p += __shfl_xor_sync(FULL, p, 4);               // 8-lane group holds score
        sc[i] = (u < UU) ? (un ? p : NEG_INF_V) : -CUDART_INF_F;
    }

    // ---- Softmax over all 50 (masked rows weight exactly 0) ----
    float mx = sc[0];
    #pragma unroll
    for (int i = 1; i < NITER; i++) mx = fmaxf(mx, sc[i]);
    mx = fmaxf(mx, __shfl_xor_sync(FULL, mx, 8));
    mx = fmaxf(mx, __shfl_xor_sync(FULL, mx, 16));

    float e[NITER];
    float s = 0.f;
    #pragma unroll
    for (int i = 0; i < NITER; i++) { e[i] = __expf(sc[i] - mx); s += e[i]; }
    s += __shfl_xor_sync(FULL, s, 8);
    s += __shfl_xor_sync(FULL, s, 16);
    float inv = __frcp_rn(s);

    // ---- Pass 2: weighted sum (weights lane-local; v=0 for skipped rows) ----
    float4 o = make_float4(0.f, 0.f, 0.f, 0.f);
    #pragma unroll
    for (int i = 0; i < NITER; i++) {
        float a = e[i] * inv;
        o.x = fmaf(a, v[i].x, o.x);
        o.y = fmaf(a, v[i].y, o.y);
        o.z = fmaf(a, v[i].z, o.z);
        o.w = fmaf(a, v[i].w, o.w);
    }

    // Reduce partial outputs across the 4 sub groups (same dims, different rows).
    #pragma unroll
    for (int off = 8; off <= 16; off <<= 1) {
        o.x += __shfl_xor_sync(FULL, o.x, off);
        o.y += __shfl_xor_sync(FULL, o.y, off);
        o.z += __shfl_xor_sync(FULL, o.z, off);
        o.w += __shfl_xor_sync(FULL, o.w, off);
    }

    // sub==0 lanes (8 of them) write the 128B output row.
    if (sub == 0) {
        float4 ci = __ldg((const float4*)(cur_item + (long long)gwarp * DD) + quad);
        float4 r = make_float4(o.x + ci.x, o.y + ci.y, o.z + ci.z, o.w + ci.w);
        ((float4*)(out + (long long)gwarp * DD))[quad] = r;
    }
}

extern "C" void kernel_launch(void* const* d_in, const int* in_sizes, int n_in,
                              void* d_out, int out_size) {
    // Select inputs by element count (robust to ordering):
    const float* cur_user = nullptr;
    const float* sim_user = nullptr;
    const float* cur_item = nullptr;
    const int*   mask     = nullptr;
    for (int i = 0; i < n_in; i++) {
        switch (in_sizes[i]) {
            case 16384:     cur_user = (const float*)d_in[i]; break;
            case 163840000: sim_user = (const float*)d_in[i]; break;
            case 3276800:   cur_item = (const float*)d_in[i]; break;
            case 5120000:   mask     = (const int*)d_in[i];   break;
        }
    }
    float* out = (float*)d_out;

    dim3 grid(SS / 8, BB);                  // 25 x 512 blocks, 8 warps/block
    DIB_attn_kernel<<<grid, 256>>>(cur_user, sim_user, cur_item, mask, out);
}